// round 4
// baseline (speedup 1.0000x reference)
#include <cuda_runtime.h>
#include <math.h>

#define NN   100000
#define FN   2
#define FE   7
#define NH   4
#define HC   32
#define EMAX 3200000
#define REGF 500

// ---------------- scratch (static device globals; no runtime alloc) ----------------
__device__ float g_xl[(size_t)NN * HC];
__device__ float g_xr[(size_t)NN * HC];
__device__ float g_h1[(size_t)NN * HC];
__device__ float g_h2[(size_t)NN * HC];
__device__ __align__(16) int g_cnt[NN];
__device__ int   g_rowptr[NN + 1];
__device__ int   g_cur[NN];
__device__ __align__(16) float g_pedge[(size_t)EMAX * 8];  // [0..6]=ea, [7]=src bits
__device__ float g_eamean[FE];     // raw sums; scaled by 1/E at use site
__device__ float g_stats[2 * HC];  // BN sums / sumsq
__device__ float g_ab[2 * HC];     // BN affine: A=scale, B=shift
__device__ float g_weff[HC + 1];   // collapsed Wreg@Wend (+ effective bias)

__device__ __forceinline__ float lrelu(float x, float s) { return x > 0.f ? x : s * x; }

// ---------------- prep kernels ----------------
__global__ void zero_kernel(int n) {
    int i = blockIdx.x * blockDim.x + threadIdx.x;
    if (i < n) g_cnt[i] = 0;
    if (blockIdx.x == 0 && threadIdx.x < FE) g_eamean[threadIdx.x] = 0.f;
}

__global__ void hist_kernel(const int* __restrict__ eidx, int E) {
    int e = blockIdx.x * blockDim.x + threadIdx.x;
    if (e < E) atomicAdd(&g_cnt[eidx[E + e]], 1);
}

// single-block scan, int4-vectorized first pass (chunk=100 keeps 16B alignment)
__global__ void scan_kernel(int n) {
    __shared__ int a[1024];
    int t = threadIdx.x;
    const int chunk = 100;
    int lo = t * chunk;
    int hi = lo + chunk; if (hi > n) hi = n; if (lo > n) lo = n;
    int s = 0;
    if (lo < hi) {
        const int4* p4 = (const int4*)(g_cnt + lo);
        int nfull = (hi - lo) >> 2;
        for (int q = 0; q < nfull; q++) {
            int4 v = p4[q];
            s += v.x + v.y + v.z + v.w;
        }
        for (int i = lo + nfull * 4; i < hi; i++) s += g_cnt[i];
    }
    a[t] = s;
    __syncthreads();
    for (int off = 1; off < 1024; off <<= 1) {
        int u = (t >= off) ? a[t - off] : 0;
        __syncthreads();
        a[t] += u;
        __syncthreads();
    }
    int run = a[t] - s;  // exclusive prefix for this chunk
    for (int i = lo; i < hi; i++) {
        int c = g_cnt[i];
        g_rowptr[i] = run;
        g_cur[i] = run;
        run += c;
    }
    if (t == 1023) g_rowptr[n] = a[1023];
}

// scatter edges into CSR order (32B record: 7 attrs + src bits); also accumulates ea sums
__global__ void scatter_kernel(const int* __restrict__ eidx, const float* __restrict__ ea, int E) {
    __shared__ float sh[FE];
    if (threadIdx.x < FE) sh[threadIdx.x] = 0.f;
    __syncthreads();
    int e = blockIdx.x * blockDim.x + threadIdx.x;
    float v[FE];
    if (e < E) {
        int s = eidx[e];
        int d = eidx[E + e];
#pragma unroll
        for (int k = 0; k < FE; k++) v[k] = ea[(size_t)e * FE + k];
        int pos = atomicAdd(&g_cur[d], 1);
        float4* rec = (float4*)(g_pedge + (size_t)pos * 8);
        rec[0] = make_float4(v[0], v[1], v[2], v[3]);
        rec[1] = make_float4(v[4], v[5], v[6], __int_as_float(s));
    } else {
#pragma unroll
        for (int k = 0; k < FE; k++) v[k] = 0.f;
    }
#pragma unroll
    for (int k = 0; k < FE; k++) {
        float x = v[k];
#pragma unroll
        for (int o = 16; o > 0; o >>= 1) x += __shfl_down_sync(0xffffffffu, x, o);
        if ((threadIdx.x & 31) == 0) atomicAdd(&sh[k], x);
    }
    __syncthreads();
    if (threadIdx.x < FE) atomicAdd(&g_eamean[threadIdx.x], sh[threadIdx.x]);
}

// parallel weff: warp w computes weff[w]; warp 0 also does the bias term
__global__ void weff_kernel(const float* __restrict__ Wreg, const float* __restrict__ breg,
                            const float* __restrict__ Wend, const float* __restrict__ bend) {
    int w = threadIdx.x >> 5, lane = threadIdx.x & 31;
    float s = 0.f;
    for (int r = lane; r < REGF; r += 32) s += Wreg[w * REGF + r] * Wend[r];
#pragma unroll
    for (int o = 16; o > 0; o >>= 1) s += __shfl_down_sync(0xffffffffu, s, o);
    if (lane == 0) g_weff[w] = s;
    if (w == 0) {
        float b = 0.f;
        for (int r = lane; r < REGF; r += 32) b += breg[r] * Wend[r];
#pragma unroll
        for (int o = 16; o > 0; o >>= 1) b += __shfl_down_sync(0xffffffffu, b, o);
        if (lane == 0) g_weff[HC] = b + bend[0];
    }
}

// ---- node transform: xl = h@Wl+bl, xr = h@Wr+br; zeros BN stats (block 0) ----
template <int F, bool BN>
__global__ void transform_kernel(const float* __restrict__ xin, int insel,
                                 const float* __restrict__ Wl, const float* __restrict__ bl,
                                 const float* __restrict__ Wr, const float* __restrict__ br,
                                 int n) {
    __shared__ float sWl[F * HC], sWr[F * HC], sb[2 * HC];
    for (int t = threadIdx.x; t < F * HC; t += blockDim.x) { sWl[t] = Wl[t]; sWr[t] = Wr[t]; }
    for (int t = threadIdx.x; t < HC; t += blockDim.x) { sb[t] = bl[t]; sb[HC + t] = br[t]; }
    if (blockIdx.x == 0 && threadIdx.x < 2 * HC) g_stats[threadIdx.x] = 0.f;
    __syncthreads();
    int i = blockIdx.x * blockDim.x + threadIdx.x;
    if (i >= n) return;
    const float* hin = (F == FN) ? xin : (insel ? g_h2 : g_h1);

    float in[F];
#pragma unroll
    for (int k = 0; k < F; k++) {
        float v = hin[(size_t)i * F + k];
        if (BN) { v = v * g_ab[k] + g_ab[HC + k]; v = lrelu(v, 0.01f); }
        in[k] = v;
    }
    float vl[HC], vr[HC];
#pragma unroll
    for (int c = 0; c < HC; c++) { vl[c] = sb[c]; vr[c] = sb[HC + c]; }
#pragma unroll
    for (int k = 0; k < F; k++) {
        float a = in[k];
#pragma unroll
        for (int c = 0; c < HC; c++) { vl[c] += a * sWl[k * HC + c]; vr[c] += a * sWr[k * HC + c]; }
    }
    float4* pl = (float4*)(g_xl + (size_t)i * HC);
    float4* pr = (float4*)(g_xr + (size_t)i * HC);
#pragma unroll
    for (int q = 0; q < 8; q++) {
        pl[q] = make_float4(vl[q * 4], vl[q * 4 + 1], vl[q * 4 + 2], vl[q * 4 + 3]);
        pr[q] = make_float4(vr[q * 4], vr[q * 4 + 1], vr[q * 4 + 2], vr[q * 4 + 3]);
    }
}

// ---------------- warp-per-node GATv2 aggregation (atomic-free hot path) --------------
// lane layout: group g = lane>>3 owns one edge slot (4 edges/iter, 8-deep unroll);
//              cs = lane&7 owns channels [cs*4, cs*4+4)
template <int MODE>
__global__ void gat_aggr_kernel(const float* __restrict__ We, const float* __restrict__ att,
                                const float* __restrict__ bias, float invE, int n, int hsel,
                                float* __restrict__ out) {
    __shared__ float sWe[FE * HC];
    __shared__ float satt[HC];
    __shared__ float smn[8];
    __shared__ float sb[HC];
    __shared__ float swf[HC + 1];
    __shared__ float sst[2 * HC];
    int t = threadIdx.x;
    if (t < FE * HC) sWe[t] = We[t];
    if (t < HC) { satt[t] = att[t]; sb[t] = bias[t]; }
    if (t < FE) smn[t] = g_eamean[t] * invE;
    if (t == FE) smn[FE] = 0.f;
    if (MODE == 0 && t < 2 * HC) sst[t] = 0.f;
    if (MODE == 1 && t < HC + 1) swf[t] = g_weff[t];
    __syncthreads();

    const unsigned FULL = 0xffffffffu;
    int lane = threadIdx.x & 31;
    int g = lane >> 3, cs = lane & 7;
    int i = (blockIdx.x * blockDim.x + threadIdx.x) >> 5;
    if (i < n) {
        int r0 = g_rowptr[i];
        int deg = g_rowptr[i + 1] - r0;
        int total = deg + 1;  // + virtual self-loop (ea = mean)
        float4 xr4 = *(const float4*)(g_xr + (size_t)i * HC + cs * 4);
        float4 att4 = *(const float4*)(satt + cs * 4);
        float4 acc = make_float4(0.f, 0.f, 0.f, 0.f);
        float den = 0.f;

        for (int cb = 0; cb < total; cb += 32) {
#pragma unroll
            for (int u = 0; u < 8; u++) {
                if (cb + u * 4 >= total) break;  // warp-uniform
                int idx = cb + u * 4 + g;
                bool valid = idx < total;
                bool isedge = idx < deg;
                float v = isedge ? g_pedge[(size_t)(r0 + idx) * 8 + cs] : smn[cs];
                float e0 = 0.f, e1 = 0.f, e2 = 0.f, e3 = 0.f;
#pragma unroll
                for (int k = 0; k < FE; k++) {
                    float a = __shfl_sync(FULL, v, g * 8 + k);
                    const float* w = sWe + k * HC + cs * 4;
                    e0 += a * w[0]; e1 += a * w[1]; e2 += a * w[2]; e3 += a * w[3];
                }
                float v7 = __shfl_sync(FULL, v, g * 8 + 7);
                int s = isedge ? __float_as_int(v7) : i;
                float4 xl4 = *(const float4*)(g_xl + (size_t)s * HC + cs * 4);
                float m0 = lrelu(xl4.x + xr4.x + e0, 0.2f);
                float m1 = lrelu(xl4.y + xr4.y + e1, 0.2f);
                float m2 = lrelu(xl4.z + xr4.z + e2, 0.2f);
                float m3 = lrelu(xl4.w + xr4.w + e3, 0.2f);
                float pl = m0 * att4.x + m1 * att4.y + m2 * att4.z + m3 * att4.w;
                float lg = pl + __shfl_xor_sync(FULL, pl, 1);
                float ex = valid ? __expf(lg) : 0.f;
                den += ex;
                acc.x += ex * xl4.x; acc.y += ex * xl4.y;
                acc.z += ex * xl4.z; acc.w += ex * xl4.w;
            }
        }
#pragma unroll
        for (int off = 8; off < 32; off <<= 1) {
            acc.x += __shfl_xor_sync(FULL, acc.x, off);
            acc.y += __shfl_xor_sync(FULL, acc.y, off);
            acc.z += __shfl_xor_sync(FULL, acc.z, off);
            acc.w += __shfl_xor_sync(FULL, acc.w, off);
            den   += __shfl_xor_sync(FULL, den,   off);
        }
        if (g == 0) {
            float inv = 1.f / (den + 1e-16f);
            float h0 = acc.x * inv + sb[cs * 4];
            float h1 = acc.y * inv + sb[cs * 4 + 1];
            float h2 = acc.z * inv + sb[cs * 4 + 2];
            float h3 = acc.w * inv + sb[cs * 4 + 3];
            if (MODE == 0) {
                float* hp = (hsel ? g_h2 : g_h1) + (size_t)i * HC + cs * 4;
                *(float4*)hp = make_float4(h0, h1, h2, h3);
                atomicAdd(&sst[cs * 4 + 0], h0);
                atomicAdd(&sst[cs * 4 + 1], h1);
                atomicAdd(&sst[cs * 4 + 2], h2);
                atomicAdd(&sst[cs * 4 + 3], h3);
                atomicAdd(&sst[HC + cs * 4 + 0], h0 * h0);
                atomicAdd(&sst[HC + cs * 4 + 1], h1 * h1);
                atomicAdd(&sst[HC + cs * 4 + 2], h2 * h2);
                atomicAdd(&sst[HC + cs * 4 + 3], h3 * h3);
            } else {
                float s = lrelu(h0, 0.01f) * swf[cs * 4]
                        + lrelu(h1, 0.01f) * swf[cs * 4 + 1]
                        + lrelu(h2, 0.01f) * swf[cs * 4 + 2]
                        + lrelu(h3, 0.01f) * swf[cs * 4 + 3];
                s += __shfl_xor_sync(0x000000ffu, s, 1);
                s += __shfl_xor_sync(0x000000ffu, s, 2);
                s += __shfl_xor_sync(0x000000ffu, s, 4);
                if (cs == 0) out[i] = s + swf[HC];
            }
        }
    }
    if (MODE == 0) {
        __syncthreads();
        if (t < 2 * HC) atomicAdd(&g_stats[t], sst[t]);
    }
}

__global__ void bn_finalize_kernel(const float* __restrict__ gamma,
                                   const float* __restrict__ beta, float invn) {
    int c = threadIdx.x;
    if (c >= HC) return;
    float mu = g_stats[c] * invn;
    float var = g_stats[HC + c] * invn - mu * mu;
    float A = rsqrtf(var + 1e-5f) * gamma[c];
    g_ab[c] = A;
    g_ab[HC + c] = beta[c] - mu * A;
}

// ---------------- launch ----------------
extern "C" void kernel_launch(void* const* d_in, const int* in_sizes, int n_in,
                              void* d_out, int out_size) {
    const float* x    = (const float*)d_in[0];
    const int*   eidx = (const int*)d_in[1];
    const float* ea   = (const float*)d_in[2];
    const float* Wl1 = (const float*)d_in[3];  const float* bl1 = (const float*)d_in[4];
    const float* Wr1 = (const float*)d_in[5];  const float* br1 = (const float*)d_in[6];
    const float* We1 = (const float*)d_in[7];  const float* att1 = (const float*)d_in[8];
    const float* b1  = (const float*)d_in[9];
    const float* Wl2 = (const float*)d_in[10]; const float* bl2 = (const float*)d_in[11];
    const float* Wr2 = (const float*)d_in[12]; const float* br2 = (const float*)d_in[13];
    const float* We2 = (const float*)d_in[14]; const float* att2 = (const float*)d_in[15];
    const float* b2  = (const float*)d_in[16];
    const float* gamma = (const float*)d_in[17]; const float* beta = (const float*)d_in[18];
    const float* Wreg = (const float*)d_in[19];  const float* breg = (const float*)d_in[20];
    const float* Wend = (const float*)d_in[21];  const float* bend = (const float*)d_in[22];
    float* out = (float*)d_out;

    int n = in_sizes[0] / FN;
    int E = in_sizes[1] / 2;
    float invE = 1.f / (float)E;
    int nbN = (n + 255) / 256;
    int nbE = (E + 255) / 256;
    int nbW = (n * 32 + 255) / 256;  // warp-per-node grid

    // launch index:                                          (ncu -s 5 -c 1 captures #5)
    zero_kernel<<<nbN, 256>>>(n);                                     // 0
    hist_kernel<<<nbE, 256>>>(eidx, E);                               // 1
    scan_kernel<<<1, 1024>>>(n);                                      // 2
    scatter_kernel<<<nbE, 256>>>(eidx, ea, E);                        // 3

    // ---- layer 1 (F=2) ----
    transform_kernel<FN, false><<<nbN, 256>>>(x, 0, Wl1, bl1, Wr1, br1, n);     // 4
    gat_aggr_kernel<0><<<nbW, 256>>>(We1, att1, b1, invE, n, 0, nullptr);       // 5 <- profiled
    bn_finalize_kernel<<<1, 32>>>(gamma, beta, 1.f / (float)n);                 // 6

    // ---- layer 2 (F=32, BN+act fused into transform) ----
    transform_kernel<HC, true><<<nbN, 256>>>(x, 0, Wl2, bl2, Wr2, br2, n);      // 7
    gat_aggr_kernel<0><<<nbW, 256>>>(We2, att2, b2, invE, n, 1, nullptr);       // 8
    bn_finalize_kernel<<<1, 32>>>(gamma, beta, 1.f / (float)n);                 // 9

    // ---- layer 3 (F=32, same weights; head fused) ----
    transform_kernel<HC, true><<<nbN, 256>>>(x, 1, Wl2, bl2, Wr2, br2, n);      // 10
    weff_kernel<<<1, 1024>>>(Wreg, breg, Wend, bend);                           // 11
    gat_aggr_kernel<1><<<nbW, 256>>>(We2, att2, b2, invE, n, 0, out);           // 12
}

// round 5
// speedup vs baseline: 1.1569x; 1.1569x over previous
#include <cuda_runtime.h>
#include <math.h>

#define NN   100000
#define FN   2
#define FE   7
#define NH   4
#define HC   32
#define EMAX 3200000
#define REGF 500

// ---------------- scratch (static device globals; no runtime alloc) ----------------
__device__ float g_xl[(size_t)NN * HC];
__device__ float g_xr[(size_t)NN * HC];
__device__ float g_h1[(size_t)NN * HC];
__device__ float g_h2[(size_t)NN * HC];
__device__ __align__(16) int g_cnt[NN];
__device__ int   g_rowptr[NN + 1];
__device__ int   g_cur[NN];
__device__ __align__(16) float g_pedge[(size_t)EMAX * 8];  // [0..6]=ea, [7]=src bits
__device__ float g_eamean[FE];     // raw sums; scaled by 1/E at use site
__device__ float g_stats[2 * HC];  // BN sums / sumsq
__device__ float g_ab[2 * HC];     // BN affine: A=scale, B=shift
__device__ float g_weff[HC + 1];   // collapsed Wreg@Wend (+ effective bias)

__device__ __forceinline__ float lrelu(float x, float s) { return x > 0.f ? x : s * x; }

// ---------------- prep kernels ----------------
__global__ void zero_kernel(int n) {
    int i = blockIdx.x * blockDim.x + threadIdx.x;
    if (i < n) g_cnt[i] = 0;
    if (blockIdx.x == 0 && threadIdx.x < FE) g_eamean[threadIdx.x] = 0.f;
}

__global__ void hist_kernel(const int* __restrict__ eidx, int E) {
    int e = blockIdx.x * blockDim.x + threadIdx.x;
    if (e < E) atomicAdd(&g_cnt[eidx[E + e]], 1);
}

// single-block scan, int4-vectorized first pass (chunk=100 keeps 16B alignment)
__global__ void scan_kernel(int n) {
    __shared__ int a[1024];
    int t = threadIdx.x;
    const int chunk = 100;
    int lo = t * chunk;
    int hi = lo + chunk; if (hi > n) hi = n; if (lo > n) lo = n;
    int s = 0;
    if (lo < hi) {
        const int4* p4 = (const int4*)(g_cnt + lo);
        int nfull = (hi - lo) >> 2;
        for (int q = 0; q < nfull; q++) {
            int4 v = p4[q];
            s += v.x + v.y + v.z + v.w;
        }
        for (int i = lo + nfull * 4; i < hi; i++) s += g_cnt[i];
    }
    a[t] = s;
    __syncthreads();
    for (int off = 1; off < 1024; off <<= 1) {
        int u = (t >= off) ? a[t - off] : 0;
        __syncthreads();
        a[t] += u;
        __syncthreads();
    }
    int run = a[t] - s;  // exclusive prefix for this chunk
    for (int i = lo; i < hi; i++) {
        int c = g_cnt[i];
        g_rowptr[i] = run;
        g_cur[i] = run;
        run += c;
    }
    if (t == 1023) g_rowptr[n] = a[1023];
}

// scatter edges into CSR order (32B record: 7 attrs + src bits); also accumulates ea sums
__global__ void scatter_kernel(const int* __restrict__ eidx, const float* __restrict__ ea, int E) {
    __shared__ float sh[FE];
    if (threadIdx.x < FE) sh[threadIdx.x] = 0.f;
    __syncthreads();
    int e = blockIdx.x * blockDim.x + threadIdx.x;
    float v[FE];
    if (e < E) {
        int s = eidx[e];
        int d = eidx[E + e];
#pragma unroll
        for (int k = 0; k < FE; k++) v[k] = ea[(size_t)e * FE + k];
        int pos = atomicAdd(&g_cur[d], 1);
        float4* rec = (float4*)(g_pedge + (size_t)pos * 8);
        rec[0] = make_float4(v[0], v[1], v[2], v[3]);
        rec[1] = make_float4(v[4], v[5], v[6], __int_as_float(s));
    } else {
#pragma unroll
        for (int k = 0; k < FE; k++) v[k] = 0.f;
    }
#pragma unroll
    for (int k = 0; k < FE; k++) {
        float x = v[k];
#pragma unroll
        for (int o = 16; o > 0; o >>= 1) x += __shfl_down_sync(0xffffffffu, x, o);
        if ((threadIdx.x & 31) == 0) atomicAdd(&sh[k], x);
    }
    __syncthreads();
    if (threadIdx.x < FE) atomicAdd(&g_eamean[threadIdx.x], sh[threadIdx.x]);
}

// parallel weff: warp w computes weff[w]; warp 0 also does the bias term
__global__ void weff_kernel(const float* __restrict__ Wreg, const float* __restrict__ breg,
                            const float* __restrict__ Wend, const float* __restrict__ bend) {
    int w = threadIdx.x >> 5, lane = threadIdx.x & 31;
    float s = 0.f;
    for (int r = lane; r < REGF; r += 32) s += Wreg[w * REGF + r] * Wend[r];
#pragma unroll
    for (int o = 16; o > 0; o >>= 1) s += __shfl_down_sync(0xffffffffu, s, o);
    if (lane == 0) g_weff[w] = s;
    if (w == 0) {
        float b = 0.f;
        for (int r = lane; r < REGF; r += 32) b += breg[r] * Wend[r];
#pragma unroll
        for (int o = 16; o > 0; o >>= 1) b += __shfl_down_sync(0xffffffffu, b, o);
        if (lane == 0) g_weff[HC] = b + bend[0];
    }
}

// ---- node transform: xl = h@Wl+bl, xr = h@Wr+br; zeros BN stats (block 0) ----
template <int F, bool BN>
__global__ void transform_kernel(const float* __restrict__ xin, int insel,
                                 const float* __restrict__ Wl, const float* __restrict__ bl,
                                 const float* __restrict__ Wr, const float* __restrict__ br,
                                 int n) {
    __shared__ float sWl[F * HC], sWr[F * HC], sb[2 * HC];
    for (int t = threadIdx.x; t < F * HC; t += blockDim.x) { sWl[t] = Wl[t]; sWr[t] = Wr[t]; }
    for (int t = threadIdx.x; t < HC; t += blockDim.x) { sb[t] = bl[t]; sb[HC + t] = br[t]; }
    if (blockIdx.x == 0 && threadIdx.x < 2 * HC) g_stats[threadIdx.x] = 0.f;
    __syncthreads();
    int i = blockIdx.x * blockDim.x + threadIdx.x;
    if (i >= n) return;
    const float* hin = (F == FN) ? xin : (insel ? g_h2 : g_h1);

    float in[F];
#pragma unroll
    for (int k = 0; k < F; k++) {
        float v = hin[(size_t)i * F + k];
        if (BN) { v = v * g_ab[k] + g_ab[HC + k]; v = lrelu(v, 0.01f); }
        in[k] = v;
    }
    float vl[HC], vr[HC];
#pragma unroll
    for (int c = 0; c < HC; c++) { vl[c] = sb[c]; vr[c] = sb[HC + c]; }
#pragma unroll
    for (int k = 0; k < F; k++) {
        float a = in[k];
#pragma unroll
        for (int c = 0; c < HC; c++) { vl[c] += a * sWl[k * HC + c]; vr[c] += a * sWr[k * HC + c]; }
    }
    float4* pl = (float4*)(g_xl + (size_t)i * HC);
    float4* pr = (float4*)(g_xr + (size_t)i * HC);
#pragma unroll
    for (int q = 0; q < 8; q++) {
        pl[q] = make_float4(vl[q * 4], vl[q * 4 + 1], vl[q * 4 + 2], vl[q * 4 + 3]);
        pr[q] = make_float4(vr[q * 4], vr[q * 4 + 1], vr[q * 4 + 2], vr[q * 4 + 3]);
    }
}

// ---------------- warp-per-node GATv2 aggregation (atomic-free hot path) --------------
// lane layout: group g = lane>>3 owns one edge slot; cs = lane&7 owns channels [cs*4,cs*4+4)
// chunk = 16 slots (4 groups x 4-deep prefetch), fully predicated, no early exit
template <int MODE>
__global__ void gat_aggr_kernel(const float* __restrict__ We, const float* __restrict__ att,
                                const float* __restrict__ bias, float invE, int n, int hsel,
                                float* __restrict__ out) {
    __shared__ float sWe[FE * HC];
    __shared__ float satt[HC];
    __shared__ float smn[8];
    __shared__ float sb[HC];
    __shared__ float swf[HC + 1];
    __shared__ float sst[2 * HC];
    int t = threadIdx.x;
    if (t < FE * HC) sWe[t] = We[t];
    if (t < HC) { satt[t] = att[t]; sb[t] = bias[t]; }
    if (t < FE) smn[t] = g_eamean[t] * invE;
    if (t == FE) smn[FE] = 0.f;
    if (MODE == 0 && t < 2 * HC) sst[t] = 0.f;
    if (MODE == 1 && t < HC + 1) swf[t] = g_weff[t];
    __syncthreads();

    const unsigned FULL = 0xffffffffu;
    int lane = threadIdx.x & 31;
    int g = lane >> 3, cs = lane & 7;
    int i = (blockIdx.x * blockDim.x + threadIdx.x) >> 5;
    if (i < n) {
        int r0 = g_rowptr[i];
        int deg = g_rowptr[i + 1] - r0;
        int total = deg + 1;  // + virtual self-loop (ea = mean)
        float4 xr4 = *(const float4*)(g_xr + (size_t)i * HC + cs * 4);
        float4 att4 = *(const float4*)(satt + cs * 4);
        float4 acc = make_float4(0.f, 0.f, 0.f, 0.f);
        float den = 0.f;
        float smncs = smn[cs];

        for (int cb = 0; cb < total; cb += 16) {
            // phase 1: 4 independent pedge loads
            float v[4];
#pragma unroll
            for (int u = 0; u < 4; u++) {
                int idx = cb + u * 4 + g;
                v[u] = (idx < deg) ? g_pedge[(size_t)(r0 + idx) * 8 + cs] : smncs;
            }
            // phase 2: extract src ids, issue 4 independent xl gathers
            float4 xl[4];
#pragma unroll
            for (int u = 0; u < 4; u++) {
                float v7 = __shfl_sync(FULL, v[u], g * 8 + 7);
                int idx = cb + u * 4 + g;
                int s = (idx < deg) ? __float_as_int(v7) : i;
                xl[u] = *(const float4*)(g_xl + (size_t)s * HC + cs * 4);
            }
            // phase 3: compute
#pragma unroll
            for (int u = 0; u < 4; u++) {
                int idx = cb + u * 4 + g;
                float e0 = 0.f, e1 = 0.f, e2 = 0.f, e3 = 0.f;
#pragma unroll
                for (int k = 0; k < FE; k++) {
                    float a = __shfl_sync(FULL, v[u], g * 8 + k);
                    const float* w = sWe + k * HC + cs * 4;
                    e0 += a * w[0]; e1 += a * w[1]; e2 += a * w[2]; e3 += a * w[3];
                }
                float m0 = lrelu(xl[u].x + xr4.x + e0, 0.2f);
                float m1 = lrelu(xl[u].y + xr4.y + e1, 0.2f);
                float m2 = lrelu(xl[u].z + xr4.z + e2, 0.2f);
                float m3 = lrelu(xl[u].w + xr4.w + e3, 0.2f);
                float pl = m0 * att4.x + m1 * att4.y + m2 * att4.z + m3 * att4.w;
                float lg = pl + __shfl_xor_sync(FULL, pl, 1);
                float ex = (idx < total) ? __expf(lg) : 0.f;
                den += ex;
                acc.x += ex * xl[u].x; acc.y += ex * xl[u].y;
                acc.z += ex * xl[u].z; acc.w += ex * xl[u].w;
            }
        }
#pragma unroll
        for (int off = 8; off < 32; off <<= 1) {
            acc.x += __shfl_xor_sync(FULL, acc.x, off);
            acc.y += __shfl_xor_sync(FULL, acc.y, off);
            acc.z += __shfl_xor_sync(FULL, acc.z, off);
            acc.w += __shfl_xor_sync(FULL, acc.w, off);
            den   += __shfl_xor_sync(FULL, den,   off);
        }
        if (g == 0) {
            float inv = 1.f / (den + 1e-16f);
            float h0 = acc.x * inv + sb[cs * 4];
            float h1 = acc.y * inv + sb[cs * 4 + 1];
            float h2 = acc.z * inv + sb[cs * 4 + 2];
            float h3 = acc.w * inv + sb[cs * 4 + 3];
            if (MODE == 0) {
                float* hp = (hsel ? g_h2 : g_h1) + (size_t)i * HC + cs * 4;
                *(float4*)hp = make_float4(h0, h1, h2, h3);
                atomicAdd(&sst[cs * 4 + 0], h0);
                atomicAdd(&sst[cs * 4 + 1], h1);
                atomicAdd(&sst[cs * 4 + 2], h2);
                atomicAdd(&sst[cs * 4 + 3], h3);
                atomicAdd(&sst[HC + cs * 4 + 0], h0 * h0);
                atomicAdd(&sst[HC + cs * 4 + 1], h1 * h1);
                atomicAdd(&sst[HC + cs * 4 + 2], h2 * h2);
                atomicAdd(&sst[HC + cs * 4 + 3], h3 * h3);
            } else {
                float s = lrelu(h0, 0.01f) * swf[cs * 4]
                        + lrelu(h1, 0.01f) * swf[cs * 4 + 1]
                        + lrelu(h2, 0.01f) * swf[cs * 4 + 2]
                        + lrelu(h3, 0.01f) * swf[cs * 4 + 3];
                s += __shfl_xor_sync(0x000000ffu, s, 1);
                s += __shfl_xor_sync(0x000000ffu, s, 2);
                s += __shfl_xor_sync(0x000000ffu, s, 4);
                if (cs == 0) out[i] = s + swf[HC];
            }
        }
    }
    if (MODE == 0) {
        __syncthreads();
        if (t < 2 * HC) atomicAdd(&g_stats[t], sst[t]);
    }
}

__global__ void bn_finalize_kernel(const float* __restrict__ gamma,
                                   const float* __restrict__ beta, float invn) {
    int c = threadIdx.x;
    if (c >= HC) return;
    float mu = g_stats[c] * invn;
    float var = g_stats[HC + c] * invn - mu * mu;
    float A = rsqrtf(var + 1e-5f) * gamma[c];
    g_ab[c] = A;
    g_ab[HC + c] = beta[c] - mu * A;
}

// ---------------- launch ----------------
extern "C" void kernel_launch(void* const* d_in, const int* in_sizes, int n_in,
                              void* d_out, int out_size) {
    const float* x    = (const float*)d_in[0];
    const int*   eidx = (const int*)d_in[1];
    const float* ea   = (const float*)d_in[2];
    const float* Wl1 = (const float*)d_in[3];  const float* bl1 = (const float*)d_in[4];
    const float* Wr1 = (const float*)d_in[5];  const float* br1 = (const float*)d_in[6];
    const float* We1 = (const float*)d_in[7];  const float* att1 = (const float*)d_in[8];
    const float* b1  = (const float*)d_in[9];
    const float* Wl2 = (const float*)d_in[10]; const float* bl2 = (const float*)d_in[11];
    const float* Wr2 = (const float*)d_in[12]; const float* br2 = (const float*)d_in[13];
    const float* We2 = (const float*)d_in[14]; const float* att2 = (const float*)d_in[15];
    const float* b2  = (const float*)d_in[16];
    const float* gamma = (const float*)d_in[17]; const float* beta = (const float*)d_in[18];
    const float* Wreg = (const float*)d_in[19];  const float* breg = (const float*)d_in[20];
    const float* Wend = (const float*)d_in[21];  const float* bend = (const float*)d_in[22];
    float* out = (float*)d_out;

    int n = in_sizes[0] / FN;
    int E = in_sizes[1] / 2;
    float invE = 1.f / (float)E;
    int nbN = (n + 255) / 256;
    int nbE = (E + 255) / 256;
    int nbW = (n * 32 + 255) / 256;  // warp-per-node grid

    // launch index:                                          (ncu -s 5 -c 1 captures #5)
    zero_kernel<<<nbN, 256>>>(n);                                     // 0
    hist_kernel<<<nbE, 256>>>(eidx, E);                               // 1
    scan_kernel<<<1, 1024>>>(n);                                      // 2
    scatter_kernel<<<nbE, 256>>>(eidx, ea, E);                        // 3

    // ---- layer 1 (F=2) ----
    transform_kernel<FN, false><<<nbN, 256>>>(x, 0, Wl1, bl1, Wr1, br1, n);     // 4
    gat_aggr_kernel<0><<<nbW, 256>>>(We1, att1, b1, invE, n, 0, nullptr);       // 5 <- profiled
    bn_finalize_kernel<<<1, 32>>>(gamma, beta, 1.f / (float)n);                 // 6

    // ---- layer 2 (F=32, BN+act fused into transform) ----
    transform_kernel<HC, true><<<nbN, 256>>>(x, 0, Wl2, bl2, Wr2, br2, n);      // 7
    gat_aggr_kernel<0><<<nbW, 256>>>(We2, att2, b2, invE, n, 1, nullptr);       // 8
    bn_finalize_kernel<<<1, 32>>>(gamma, beta, 1.f / (float)n);                 // 9

    // ---- layer 3 (F=32, same weights; head fused) ----
    transform_kernel<HC, true><<<nbN, 256>>>(x, 1, Wl2, bl2, Wr2, br2, n);      // 10
    weff_kernel<<<1, 1024>>>(Wreg, breg, Wend, bend);                           // 11
    gat_aggr_kernel<1><<<nbW, 256>>>(We2, att2, b2, invE, n, 0, out);           // 12
}

// round 6
// speedup vs baseline: 1.1739x; 1.0147x over previous
#include <cuda_runtime.h>
#include <math.h>

#define NN   100000
#define FN   2
#define FE   7
#define NH   4
#define HC   32
#define EMAX 3200000
#define REGF 500

// ---------------- scratch (static device globals; no runtime alloc) ----------------
__device__ float g_xl[(size_t)NN * HC];
__device__ float g_xr[(size_t)NN * HC];
__device__ float g_h1[(size_t)NN * HC];
__device__ float g_h2[(size_t)NN * HC];
__device__ __align__(16) int g_cnt[NN];
__device__ int   g_rowptr[NN + 1];
__device__ int   g_cur[NN];
__device__ __align__(16) float g_pedge[(size_t)EMAX * 8];  // [0..6]=ea, [7]=src bits
__device__ float g_eamean[FE];     // raw sums; scaled by 1/E at use site
__device__ float g_stats[2 * HC];  // BN sums / sumsq
__device__ float g_ab[2 * HC];     // BN affine: A=scale, B=shift
__device__ float g_weff[HC + 1];   // collapsed Wreg@Wend (+ effective bias)

__device__ __forceinline__ float lrelu(float x, float s) { return x > 0.f ? x : s * x; }

// ---------------- prep kernels ----------------
__global__ void zero_kernel(int n) {
    int i = blockIdx.x * blockDim.x + threadIdx.x;
    if (i < n) g_cnt[i] = 0;
    if (blockIdx.x == 0 && threadIdx.x < FE) g_eamean[threadIdx.x] = 0.f;
}

__global__ void hist_kernel(const int* __restrict__ eidx, int E) {
    int e = blockIdx.x * blockDim.x + threadIdx.x;
    if (e < E) atomicAdd(&g_cnt[eidx[E + e]], 1);
}

// single-block scan, int4-vectorized first pass (chunk=100 keeps 16B alignment)
__global__ void scan_kernel(int n) {
    __shared__ int a[1024];
    int t = threadIdx.x;
    const int chunk = 100;
    int lo = t * chunk;
    int hi = lo + chunk; if (hi > n) hi = n; if (lo > n) lo = n;
    int s = 0;
    if (lo < hi) {
        const int4* p4 = (const int4*)(g_cnt + lo);
        int nfull = (hi - lo) >> 2;
        for (int q = 0; q < nfull; q++) {
            int4 v = p4[q];
            s += v.x + v.y + v.z + v.w;
        }
        for (int i = lo + nfull * 4; i < hi; i++) s += g_cnt[i];
    }
    a[t] = s;
    __syncthreads();
    for (int off = 1; off < 1024; off <<= 1) {
        int u = (t >= off) ? a[t - off] : 0;
        __syncthreads();
        a[t] += u;
        __syncthreads();
    }
    int run = a[t] - s;  // exclusive prefix for this chunk
    for (int i = lo; i < hi; i++) {
        int c = g_cnt[i];
        g_rowptr[i] = run;
        g_cur[i] = run;
        run += c;
    }
    if (t == 1023) g_rowptr[n] = a[1023];
}

// scatter edges into CSR order (32B record: 7 attrs + src bits); also accumulates ea sums
__global__ void scatter_kernel(const int* __restrict__ eidx, const float* __restrict__ ea, int E) {
    __shared__ float sh[FE];
    if (threadIdx.x < FE) sh[threadIdx.x] = 0.f;
    __syncthreads();
    int e = blockIdx.x * blockDim.x + threadIdx.x;
    float v[FE];
    if (e < E) {
        int s = eidx[e];
        int d = eidx[E + e];
#pragma unroll
        for (int k = 0; k < FE; k++) v[k] = ea[(size_t)e * FE + k];
        int pos = atomicAdd(&g_cur[d], 1);
        float4* rec = (float4*)(g_pedge + (size_t)pos * 8);
        rec[0] = make_float4(v[0], v[1], v[2], v[3]);
        rec[1] = make_float4(v[4], v[5], v[6], __int_as_float(s));
    } else {
#pragma unroll
        for (int k = 0; k < FE; k++) v[k] = 0.f;
    }
#pragma unroll
    for (int k = 0; k < FE; k++) {
        float x = v[k];
#pragma unroll
        for (int o = 16; o > 0; o >>= 1) x += __shfl_down_sync(0xffffffffu, x, o);
        if ((threadIdx.x & 31) == 0) atomicAdd(&sh[k], x);
    }
    __syncthreads();
    if (threadIdx.x < FE) atomicAdd(&g_eamean[threadIdx.x], sh[threadIdx.x]);
}

// parallel weff: warp w computes weff[w]; warp 0 also does the bias term
__global__ void weff_kernel(const float* __restrict__ Wreg, const float* __restrict__ breg,
                            const float* __restrict__ Wend, const float* __restrict__ bend) {
    int w = threadIdx.x >> 5, lane = threadIdx.x & 31;
    float s = 0.f;
    for (int r = lane; r < REGF; r += 32) s += Wreg[w * REGF + r] * Wend[r];
#pragma unroll
    for (int o = 16; o > 0; o >>= 1) s += __shfl_down_sync(0xffffffffu, s, o);
    if (lane == 0) g_weff[w] = s;
    if (w == 0) {
        float b = 0.f;
        for (int r = lane; r < REGF; r += 32) b += breg[r] * Wend[r];
#pragma unroll
        for (int o = 16; o > 0; o >>= 1) b += __shfl_down_sync(0xffffffffu, b, o);
        if (lane == 0) g_weff[HC] = b + bend[0];
    }
}

// ---- node transform: xl = h@Wl+bl, xr = h@Wr+br; zeros BN stats (block 0) ----
template <int F, bool BN>
__global__ void transform_kernel(const float* __restrict__ xin, int insel,
                                 const float* __restrict__ Wl, const float* __restrict__ bl,
                                 const float* __restrict__ Wr, const float* __restrict__ br,
                                 int n) {
    __shared__ float sWl[F * HC], sWr[F * HC], sb[2 * HC];
    for (int t = threadIdx.x; t < F * HC; t += blockDim.x) { sWl[t] = Wl[t]; sWr[t] = Wr[t]; }
    for (int t = threadIdx.x; t < HC; t += blockDim.x) { sb[t] = bl[t]; sb[HC + t] = br[t]; }
    if (blockIdx.x == 0 && threadIdx.x < 2 * HC) g_stats[threadIdx.x] = 0.f;
    __syncthreads();
    int i = blockIdx.x * blockDim.x + threadIdx.x;
    if (i >= n) return;
    const float* hin = (F == FN) ? xin : (insel ? g_h2 : g_h1);

    float in[F];
#pragma unroll
    for (int k = 0; k < F; k++) {
        float v = hin[(size_t)i * F + k];
        if (BN) { v = v * g_ab[k] + g_ab[HC + k]; v = lrelu(v, 0.01f); }
        in[k] = v;
    }
    float vl[HC], vr[HC];
#pragma unroll
    for (int c = 0; c < HC; c++) { vl[c] = sb[c]; vr[c] = sb[HC + c]; }
#pragma unroll
    for (int k = 0; k < F; k++) {
        float a = in[k];
#pragma unroll
        for (int c = 0; c < HC; c++) { vl[c] += a * sWl[k * HC + c]; vr[c] += a * sWr[k * HC + c]; }
    }
    float4* pl = (float4*)(g_xl + (size_t)i * HC);
    float4* pr = (float4*)(g_xr + (size_t)i * HC);
#pragma unroll
    for (int q = 0; q < 8; q++) {
        pl[q] = make_float4(vl[q * 4], vl[q * 4 + 1], vl[q * 4 + 2], vl[q * 4 + 3]);
        pr[q] = make_float4(vr[q * 4], vr[q * 4 + 1], vr[q * 4 + 2], vr[q * 4 + 3]);
    }
}

// ---------------- warp-per-node GATv2 aggregation, software-pipelined ------------------
// lane layout: group g = lane>>3 owns one edge slot; cs = lane&7 owns channels [cs*4,cs*4+4)
// chunk = 16 slots (4 groups x 4-deep). Pipeline: pedge prefetched 1 chunk ahead;
// xl gathers issued before eattr compute (which has no xl dependency) to hide L2 latency.
template <int MODE>
__global__ void __launch_bounds__(256)
gat_aggr_kernel(const float* __restrict__ We, const float* __restrict__ att,
                const float* __restrict__ bias, float invE, int n, int hsel,
                float* __restrict__ out) {
    __shared__ float sWe[FE * HC];
    __shared__ float satt[HC];
    __shared__ float smn[8];
    __shared__ float sb[HC];
    __shared__ float swf[HC + 1];
    __shared__ float sst[2 * HC];
    int t = threadIdx.x;
    if (t < FE * HC) sWe[t] = We[t];
    if (t < HC) { satt[t] = att[t]; sb[t] = bias[t]; }
    if (t < FE) smn[t] = g_eamean[t] * invE;
    if (t == FE) smn[FE] = 0.f;
    if (MODE == 0 && t < 2 * HC) sst[t] = 0.f;
    if (MODE == 1 && t < HC + 1) swf[t] = g_weff[t];
    __syncthreads();

    const unsigned FULL = 0xffffffffu;
    int lane = threadIdx.x & 31;
    int g = lane >> 3, cs = lane & 7;
    int i = (blockIdx.x * blockDim.x + threadIdx.x) >> 5;
    if (i < n) {
        int r0 = g_rowptr[i];
        int deg = g_rowptr[i + 1] - r0;
        int total = deg + 1;  // + virtual self-loop (ea = mean)
        float4 xr4 = *(const float4*)(g_xr + (size_t)i * HC + cs * 4);
        float4 att4 = *(const float4*)(satt + cs * 4);
        float4 acc = make_float4(0.f, 0.f, 0.f, 0.f);
        float den = 0.f;
        float smncs = smn[cs];
        int nchunks = (total + 15) >> 4;

        // prologue: issue chunk-0 pedge loads
        float vn[4];
#pragma unroll
        for (int u = 0; u < 4; u++) {
            int idx = u * 4 + g;
            vn[u] = (idx < deg) ? g_pedge[(size_t)(r0 + idx) * 8 + cs] : smncs;
        }

        for (int c = 0; c < nchunks; c++) {
            int cb = c << 4;
            float v[4];
#pragma unroll
            for (int u = 0; u < 4; u++) v[u] = vn[u];

            // extract src ids, issue 4 xl gathers (only dependency: v)
            float4 xl[4];
#pragma unroll
            for (int u = 0; u < 4; u++) {
                float v7 = __shfl_sync(FULL, v[u], g * 8 + 7);
                int idx = cb + u * 4 + g;
                int s = (idx < deg) ? __float_as_int(v7) : i;
                xl[u] = *(const float4*)(g_xl + (size_t)s * HC + cs * 4);
            }

            // prefetch next chunk's pedge (lands during this chunk's compute)
#pragma unroll
            for (int u = 0; u < 4; u++) {
                int idx = cb + 16 + u * 4 + g;
                vn[u] = (idx < deg) ? g_pedge[(size_t)(r0 + idx) * 8 + cs] : smncs;
            }

            // eattr transforms: depend only on v — covers xl gather latency
            float e[4][4];
#pragma unroll
            for (int u = 0; u < 4; u++) {
                float e0 = 0.f, e1 = 0.f, e2 = 0.f, e3 = 0.f;
#pragma unroll
                for (int k = 0; k < FE; k++) {
                    float a = __shfl_sync(FULL, v[u], g * 8 + k);
                    const float* w = sWe + k * HC + cs * 4;
                    e0 += a * w[0]; e1 += a * w[1]; e2 += a * w[2]; e3 += a * w[3];
                }
                e[u][0] = e0; e[u][1] = e1; e[u][2] = e2; e[u][3] = e3;
            }

            // consume xl
#pragma unroll
            for (int u = 0; u < 4; u++) {
                int idx = cb + u * 4 + g;
                float m0 = lrelu(xl[u].x + xr4.x + e[u][0], 0.2f);
                float m1 = lrelu(xl[u].y + xr4.y + e[u][1], 0.2f);
                float m2 = lrelu(xl[u].z + xr4.z + e[u][2], 0.2f);
                float m3 = lrelu(xl[u].w + xr4.w + e[u][3], 0.2f);
                float pl = m0 * att4.x + m1 * att4.y + m2 * att4.z + m3 * att4.w;
                float lg = pl + __shfl_xor_sync(FULL, pl, 1);
                float ex = (idx < total) ? __expf(lg) : 0.f;
                den += ex;
                acc.x += ex * xl[u].x; acc.y += ex * xl[u].y;
                acc.z += ex * xl[u].z; acc.w += ex * xl[u].w;
            }
        }
#pragma unroll
        for (int off = 8; off < 32; off <<= 1) {
            acc.x += __shfl_xor_sync(FULL, acc.x, off);
            acc.y += __shfl_xor_sync(FULL, acc.y, off);
            acc.z += __shfl_xor_sync(FULL, acc.z, off);
            acc.w += __shfl_xor_sync(FULL, acc.w, off);
            den   += __shfl_xor_sync(FULL, den,   off);
        }
        if (g == 0) {
            float inv = 1.f / (den + 1e-16f);
            float h0 = acc.x * inv + sb[cs * 4];
            float h1 = acc.y * inv + sb[cs * 4 + 1];
            float h2 = acc.z * inv + sb[cs * 4 + 2];
            float h3 = acc.w * inv + sb[cs * 4 + 3];
            if (MODE == 0) {
                float* hp = (hsel ? g_h2 : g_h1) + (size_t)i * HC + cs * 4;
                *(float4*)hp = make_float4(h0, h1, h2, h3);
                atomicAdd(&sst[cs * 4 + 0], h0);
                atomicAdd(&sst[cs * 4 + 1], h1);
                atomicAdd(&sst[cs * 4 + 2], h2);
                atomicAdd(&sst[cs * 4 + 3], h3);
                atomicAdd(&sst[HC + cs * 4 + 0], h0 * h0);
                atomicAdd(&sst[HC + cs * 4 + 1], h1 * h1);
                atomicAdd(&sst[HC + cs * 4 + 2], h2 * h2);
                atomicAdd(&sst[HC + cs * 4 + 3], h3 * h3);
            } else {
                float s = lrelu(h0, 0.01f) * swf[cs * 4]
                        + lrelu(h1, 0.01f) * swf[cs * 4 + 1]
                        + lrelu(h2, 0.01f) * swf[cs * 4 + 2]
                        + lrelu(h3, 0.01f) * swf[cs * 4 + 3];
                s += __shfl_xor_sync(0x000000ffu, s, 1);
                s += __shfl_xor_sync(0x000000ffu, s, 2);
                s += __shfl_xor_sync(0x000000ffu, s, 4);
                if (cs == 0) out[i] = s + swf[HC];
            }
        }
    }
    if (MODE == 0) {
        __syncthreads();
        if (t < 2 * HC) atomicAdd(&g_stats[t], sst[t]);
    }
}

__global__ void bn_finalize_kernel(const float* __restrict__ gamma,
                                   const float* __restrict__ beta, float invn) {
    int c = threadIdx.x;
    if (c >= HC) return;
    float mu = g_stats[c] * invn;
    float var = g_stats[HC + c] * invn - mu * mu;
    float A = rsqrtf(var + 1e-5f) * gamma[c];
    g_ab[c] = A;
    g_ab[HC + c] = beta[c] - mu * A;
}

// ---------------- launch ----------------
extern "C" void kernel_launch(void* const* d_in, const int* in_sizes, int n_in,
                              void* d_out, int out_size) {
    const float* x    = (const float*)d_in[0];
    const int*   eidx = (const int*)d_in[1];
    const float* ea   = (const float*)d_in[2];
    const float* Wl1 = (const float*)d_in[3];  const float* bl1 = (const float*)d_in[4];
    const float* Wr1 = (const float*)d_in[5];  const float* br1 = (const float*)d_in[6];
    const float* We1 = (const float*)d_in[7];  const float* att1 = (const float*)d_in[8];
    const float* b1  = (const float*)d_in[9];
    const float* Wl2 = (const float*)d_in[10]; const float* bl2 = (const float*)d_in[11];
    const float* Wr2 = (const float*)d_in[12]; const float* br2 = (const float*)d_in[13];
    const float* We2 = (const float*)d_in[14]; const float* att2 = (const float*)d_in[15];
    const float* b2  = (const float*)d_in[16];
    const float* gamma = (const float*)d_in[17]; const float* beta = (const float*)d_in[18];
    const float* Wreg = (const float*)d_in[19];  const float* breg = (const float*)d_in[20];
    const float* Wend = (const float*)d_in[21];  const float* bend = (const float*)d_in[22];
    float* out = (float*)d_out;

    int n = in_sizes[0] / FN;
    int E = in_sizes[1] / 2;
    float invE = 1.f / (float)E;
    int nbN = (n + 255) / 256;
    int nbE = (E + 255) / 256;
    int nbW = (n * 32 + 255) / 256;  // warp-per-node grid

    zero_kernel<<<nbN, 256>>>(n);                                     // 0
    hist_kernel<<<nbE, 256>>>(eidx, E);                               // 1
    scan_kernel<<<1, 1024>>>(n);                                      // 2
    scatter_kernel<<<nbE, 256>>>(eidx, ea, E);                        // 3

    // ---- layer 1 (F=2) ----
    transform_kernel<FN, false><<<nbN, 256>>>(x, 0, Wl1, bl1, Wr1, br1, n);     // 4
    gat_aggr_kernel<0><<<nbW, 256>>>(We1, att1, b1, invE, n, 0, nullptr);       // 5
    bn_finalize_kernel<<<1, 32>>>(gamma, beta, 1.f / (float)n);                 // 6

    // ---- layer 2 (F=32, BN+act fused into transform) ----
    transform_kernel<HC, true><<<nbN, 256>>>(x, 0, Wl2, bl2, Wr2, br2, n);      // 7
    gat_aggr_kernel<0><<<nbW, 256>>>(We2, att2, b2, invE, n, 1, nullptr);       // 8
    bn_finalize_kernel<<<1, 32>>>(gamma, beta, 1.f / (float)n);                 // 9

    // ---- layer 3 (F=32, same weights; head fused) ----
    transform_kernel<HC, true><<<nbN, 256>>>(x, 1, Wl2, bl2, Wr2, br2, n);      // 10
    weff_kernel<<<1, 1024>>>(Wreg, breg, Wend, bend);                           // 11
    gat_aggr_kernel<1><<<nbW, 256>>>(We2, att2, b2, invE, n, 0, out);           // 12
}

// round 7
// speedup vs baseline: 1.3165x; 1.1215x over previous
#include <cuda_runtime.h>
#include <math.h>

#define NN   100000
#define FN   2
#define FE   7
#define NH   4
#define HC   32
#define EMAX 3200000
#define REGF 500

// ---------------- scratch (static device globals; no runtime alloc) ----------------
__device__ float g_xl[(size_t)NN * HC];
__device__ float g_xr[(size_t)NN * HC];
__device__ float g_h1[(size_t)NN * HC];
__device__ float g_h2[(size_t)NN * HC];
__device__ __align__(16) int g_cnt[NN];
__device__ int   g_rowptr[NN + 1];
__device__ int   g_cur[NN];
__device__ __align__(16) float g_pedge[(size_t)EMAX * 8];  // [0..6]=ea, [7]=src bits
__device__ float g_eamean[FE];     // raw sums; scaled by 1/E at use site
__device__ float g_stats[2 * HC];  // BN sums / sumsq
__device__ float g_ab[2 * HC];     // BN affine: A=scale, B=shift
__device__ float g_weff[HC + 1];   // collapsed Wreg@Wend (+ effective bias)

__device__ __forceinline__ float lrelu(float x, float s) { return x > 0.f ? x : s * x; }

// ---------------- prep kernels ----------------
__global__ void zero_kernel(int n) {
    int i = blockIdx.x * blockDim.x + threadIdx.x;
    if (i < n) g_cnt[i] = 0;
    if (blockIdx.x == 0 && threadIdx.x < FE) g_eamean[threadIdx.x] = 0.f;
}

__global__ void hist_kernel(const int* __restrict__ eidx, int E) {
    int e = blockIdx.x * blockDim.x + threadIdx.x;
    if (e < E) atomicAdd(&g_cnt[eidx[E + e]], 1);
}

// single-block scan, int4-vectorized first pass (chunk=100 keeps 16B alignment)
__global__ void scan_kernel(int n) {
    __shared__ int a[1024];
    int t = threadIdx.x;
    const int chunk = 100;
    int lo = t * chunk;
    int hi = lo + chunk; if (hi > n) hi = n; if (lo > n) lo = n;
    int s = 0;
    if (lo < hi) {
        const int4* p4 = (const int4*)(g_cnt + lo);
        int nfull = (hi - lo) >> 2;
        for (int q = 0; q < nfull; q++) {
            int4 v = p4[q];
            s += v.x + v.y + v.z + v.w;
        }
        for (int i = lo + nfull * 4; i < hi; i++) s += g_cnt[i];
    }
    a[t] = s;
    __syncthreads();
    for (int off = 1; off < 1024; off <<= 1) {
        int u = (t >= off) ? a[t - off] : 0;
        __syncthreads();
        a[t] += u;
        __syncthreads();
    }
    int run = a[t] - s;  // exclusive prefix for this chunk
    for (int i = lo; i < hi; i++) {
        int c = g_cnt[i];
        g_rowptr[i] = run;
        g_cur[i] = run;
        run += c;
    }
    if (t == 1023) g_rowptr[n] = a[1023];
}

// scatter edges into CSR order (32B record: 7 attrs + src bits); also accumulates ea sums
__global__ void scatter_kernel(const int* __restrict__ eidx, const float* __restrict__ ea, int E) {
    __shared__ float sh[FE];
    if (threadIdx.x < FE) sh[threadIdx.x] = 0.f;
    __syncthreads();
    int e = blockIdx.x * blockDim.x + threadIdx.x;
    float v[FE];
    if (e < E) {
        int s = eidx[e];
        int d = eidx[E + e];
#pragma unroll
        for (int k = 0; k < FE; k++) v[k] = ea[(size_t)e * FE + k];
        int pos = atomicAdd(&g_cur[d], 1);
        float4* rec = (float4*)(g_pedge + (size_t)pos * 8);
        rec[0] = make_float4(v[0], v[1], v[2], v[3]);
        rec[1] = make_float4(v[4], v[5], v[6], __int_as_float(s));
    } else {
#pragma unroll
        for (int k = 0; k < FE; k++) v[k] = 0.f;
    }
#pragma unroll
    for (int k = 0; k < FE; k++) {
        float x = v[k];
#pragma unroll
        for (int o = 16; o > 0; o >>= 1) x += __shfl_down_sync(0xffffffffu, x, o);
        if ((threadIdx.x & 31) == 0) atomicAdd(&sh[k], x);
    }
    __syncthreads();
    if (threadIdx.x < FE) atomicAdd(&g_eamean[threadIdx.x], sh[threadIdx.x]);
}

// parallel weff: warp w computes weff[w]; warp 0 also does the bias term
__global__ void weff_kernel(const float* __restrict__ Wreg, const float* __restrict__ breg,
                            const float* __restrict__ Wend, const float* __restrict__ bend) {
    int w = threadIdx.x >> 5, lane = threadIdx.x & 31;
    float s = 0.f;
    for (int r = lane; r < REGF; r += 32) s += Wreg[w * REGF + r] * Wend[r];
#pragma unroll
    for (int o = 16; o > 0; o >>= 1) s += __shfl_down_sync(0xffffffffu, s, o);
    if (lane == 0) g_weff[w] = s;
    if (w == 0) {
        float b = 0.f;
        for (int r = lane; r < REGF; r += 32) b += breg[r] * Wend[r];
#pragma unroll
        for (int o = 16; o > 0; o >>= 1) b += __shfl_down_sync(0xffffffffu, b, o);
        if (lane == 0) g_weff[HC] = b + bend[0];
    }
}

// ---- node transform: xl = h@Wl+bl, xr = h@Wr+br; zeros BN stats (block 0) ----
template <int F, bool BN>
__global__ void transform_kernel(const float* __restrict__ xin, int insel,
                                 const float* __restrict__ Wl, const float* __restrict__ bl,
                                 const float* __restrict__ Wr, const float* __restrict__ br,
                                 int n) {
    __shared__ float sWl[F * HC], sWr[F * HC], sb[2 * HC];
    for (int t = threadIdx.x; t < F * HC; t += blockDim.x) { sWl[t] = Wl[t]; sWr[t] = Wr[t]; }
    for (int t = threadIdx.x; t < HC; t += blockDim.x) { sb[t] = bl[t]; sb[HC + t] = br[t]; }
    if (blockIdx.x == 0 && threadIdx.x < 2 * HC) g_stats[threadIdx.x] = 0.f;
    __syncthreads();
    int i = blockIdx.x * blockDim.x + threadIdx.x;
    if (i >= n) return;
    const float* hin = (F == FN) ? xin : (insel ? g_h2 : g_h1);

    float in[F];
#pragma unroll
    for (int k = 0; k < F; k++) {
        float v = hin[(size_t)i * F + k];
        if (BN) { v = v * g_ab[k] + g_ab[HC + k]; v = lrelu(v, 0.01f); }
        in[k] = v;
    }
    float vl[HC], vr[HC];
#pragma unroll
    for (int c = 0; c < HC; c++) { vl[c] = sb[c]; vr[c] = sb[HC + c]; }
#pragma unroll
    for (int k = 0; k < F; k++) {
        float a = in[k];
#pragma unroll
        for (int c = 0; c < HC; c++) { vl[c] += a * sWl[k * HC + c]; vr[c] += a * sWr[k * HC + c]; }
    }
    float4* pl = (float4*)(g_xl + (size_t)i * HC);
    float4* pr = (float4*)(g_xr + (size_t)i * HC);
#pragma unroll
    for (int q = 0; q < 8; q++) {
        pl[q] = make_float4(vl[q * 4], vl[q * 4 + 1], vl[q * 4 + 2], vl[q * 4 + 3]);
        pr[q] = make_float4(vr[q * 4], vr[q * 4 + 1], vr[q * 4 + 2], vr[q * 4 + 3]);
    }
}

// ---------------- warp-per-node GATv2 aggregation, software-pipelined ------------------
// lane layout: group g = lane>>3 owns one edge slot; cs = lane&7 owns channels [cs*4,cs*4+4)
// We slice held in 28 REGISTERS per lane (no LDS in the hot loop).
template <int MODE>
__global__ void __launch_bounds__(256, 2)
gat_aggr_kernel(const float* __restrict__ We, const float* __restrict__ att,
                const float* __restrict__ bias, float invE, int n, int hsel,
                float* __restrict__ out) {
    __shared__ float smn[8];
    __shared__ float sb[HC];
    __shared__ float swf[HC + 1];
    __shared__ float sst[2 * HC];
    int t = threadIdx.x;
    if (t < HC) sb[t] = bias[t];
    if (t < FE) smn[t] = g_eamean[t] * invE;
    if (t == FE) smn[FE] = 0.f;
    if (MODE == 0 && t < 2 * HC) sst[t] = 0.f;
    if (MODE == 1 && t < HC + 1) swf[t] = g_weff[t];
    __syncthreads();

    const unsigned FULL = 0xffffffffu;
    int lane = threadIdx.x & 31;
    int g = lane >> 3, cs = lane & 7;

    // per-lane register copies of the We slice and att slice for channels cs*4..cs*4+3
    float4 wk[FE];
#pragma unroll
    for (int k = 0; k < FE; k++) wk[k] = *(const float4*)(We + k * HC + cs * 4);
    float4 att4 = *(const float4*)(att + cs * 4);

    int i = (blockIdx.x * blockDim.x + threadIdx.x) >> 5;
    if (i < n) {
        int r0 = g_rowptr[i];
        int deg = g_rowptr[i + 1] - r0;
        int total = deg + 1;  // + virtual self-loop (ea = mean)
        float4 xr4 = *(const float4*)(g_xr + (size_t)i * HC + cs * 4);
        float4 acc = make_float4(0.f, 0.f, 0.f, 0.f);
        float den = 0.f;
        float smncs = smn[cs];
        int nchunks = (total + 15) >> 4;

        // prologue: issue chunk-0 pedge loads
        float vn[4];
#pragma unroll
        for (int u = 0; u < 4; u++) {
            int idx = u * 4 + g;
            vn[u] = (idx < deg) ? g_pedge[(size_t)(r0 + idx) * 8 + cs] : smncs;
        }

        for (int c = 0; c < nchunks; c++) {
            int cb = c << 4;
            float v[4];
#pragma unroll
            for (int u = 0; u < 4; u++) v[u] = vn[u];

            // extract src ids, issue 4 xl gathers (only dependency: v)
            float4 xl[4];
#pragma unroll
            for (int u = 0; u < 4; u++) {
                float v7 = __shfl_sync(FULL, v[u], g * 8 + 7);
                int idx = cb + u * 4 + g;
                int s = (idx < deg) ? __float_as_int(v7) : i;
                xl[u] = *(const float4*)(g_xl + (size_t)s * HC + cs * 4);
            }

            // prefetch next chunk's pedge (lands during this chunk's compute)
#pragma unroll
            for (int u = 0; u < 4; u++) {
                int idx = cb + 16 + u * 4 + g;
                vn[u] = (idx < deg) ? g_pedge[(size_t)(r0 + idx) * 8 + cs] : smncs;
            }

            // eattr transforms from REGISTERS (covers xl gather latency)
            float e[4][4];
#pragma unroll
            for (int u = 0; u < 4; u++) {
                float e0 = 0.f, e1 = 0.f, e2 = 0.f, e3 = 0.f;
#pragma unroll
                for (int k = 0; k < FE; k++) {
                    float a = __shfl_sync(FULL, v[u], g * 8 + k);
                    e0 += a * wk[k].x; e1 += a * wk[k].y;
                    e2 += a * wk[k].z; e3 += a * wk[k].w;
                }
                e[u][0] = e0; e[u][1] = e1; e[u][2] = e2; e[u][3] = e3;
            }

            // consume xl
#pragma unroll
            for (int u = 0; u < 4; u++) {
                int idx = cb + u * 4 + g;
                float m0 = lrelu(xl[u].x + xr4.x + e[u][0], 0.2f);
                float m1 = lrelu(xl[u].y + xr4.y + e[u][1], 0.2f);
                float m2 = lrelu(xl[u].z + xr4.z + e[u][2], 0.2f);
                float m3 = lrelu(xl[u].w + xr4.w + e[u][3], 0.2f);
                float pl = m0 * att4.x + m1 * att4.y + m2 * att4.z + m3 * att4.w;
                float lg = pl + __shfl_xor_sync(FULL, pl, 1);
                float ex = (idx < total) ? __expf(lg) : 0.f;
                den += ex;
                acc.x += ex * xl[u].x; acc.y += ex * xl[u].y;
                acc.z += ex * xl[u].z; acc.w += ex * xl[u].w;
            }
        }
#pragma unroll
        for (int off = 8; off < 32; off <<= 1) {
            acc.x += __shfl_xor_sync(FULL, acc.x, off);
            acc.y += __shfl_xor_sync(FULL, acc.y, off);
            acc.z += __shfl_xor_sync(FULL, acc.z, off);
            acc.w += __shfl_xor_sync(FULL, acc.w, off);
            den   += __shfl_xor_sync(FULL, den,   off);
        }
        if (g == 0) {
            float inv = 1.f / (den + 1e-16f);
            float h0 = acc.x * inv + sb[cs * 4];
            float h1 = acc.y * inv + sb[cs * 4 + 1];
            float h2 = acc.z * inv + sb[cs * 4 + 2];
            float h3 = acc.w * inv + sb[cs * 4 + 3];
            if (MODE == 0) {
                float* hp = (hsel ? g_h2 : g_h1) + (size_t)i * HC + cs * 4;
                *(float4*)hp = make_float4(h0, h1, h2, h3);
                atomicAdd(&sst[cs * 4 + 0], h0);
                atomicAdd(&sst[cs * 4 + 1], h1);
                atomicAdd(&sst[cs * 4 + 2], h2);
                atomicAdd(&sst[cs * 4 + 3], h3);
                atomicAdd(&sst[HC + cs * 4 + 0], h0 * h0);
                atomicAdd(&sst[HC + cs * 4 + 1], h1 * h1);
                atomicAdd(&sst[HC + cs * 4 + 2], h2 * h2);
                atomicAdd(&sst[HC + cs * 4 + 3], h3 * h3);
            } else {
                float s = lrelu(h0, 0.01f) * swf[cs * 4]
                        + lrelu(h1, 0.01f) * swf[cs * 4 + 1]
                        + lrelu(h2, 0.01f) * swf[cs * 4 + 2]
                        + lrelu(h3, 0.01f) * swf[cs * 4 + 3];
                s += __shfl_xor_sync(0x000000ffu, s, 1);
                s += __shfl_xor_sync(0x000000ffu, s, 2);
                s += __shfl_xor_sync(0x000000ffu, s, 4);
                if (cs == 0) out[i] = s + swf[HC];
            }
        }
    }
    if (MODE == 0) {
        __syncthreads();
        if (t < 2 * HC) atomicAdd(&g_stats[t], sst[t]);
    }
}

__global__ void bn_finalize_kernel(const float* __restrict__ gamma,
                                   const float* __restrict__ beta, float invn) {
    int c = threadIdx.x;
    if (c >= HC) return;
    float mu = g_stats[c] * invn;
    float var = g_stats[HC + c] * invn - mu * mu;
    float A = rsqrtf(var + 1e-5f) * gamma[c];
    g_ab[c] = A;
    g_ab[HC + c] = beta[c] - mu * A;
}

// ---------------- launch ----------------
extern "C" void kernel_launch(void* const* d_in, const int* in_sizes, int n_in,
                              void* d_out, int out_size) {
    const float* x    = (const float*)d_in[0];
    const int*   eidx = (const int*)d_in[1];
    const float* ea   = (const float*)d_in[2];
    const float* Wl1 = (const float*)d_in[3];  const float* bl1 = (const float*)d_in[4];
    const float* Wr1 = (const float*)d_in[5];  const float* br1 = (const float*)d_in[6];
    const float* We1 = (const float*)d_in[7];  const float* att1 = (const float*)d_in[8];
    const float* b1  = (const float*)d_in[9];
    const float* Wl2 = (const float*)d_in[10]; const float* bl2 = (const float*)d_in[11];
    const float* Wr2 = (const float*)d_in[12]; const float* br2 = (const float*)d_in[13];
    const float* We2 = (const float*)d_in[14]; const float* att2 = (const float*)d_in[15];
    const float* b2  = (const float*)d_in[16];
    const float* gamma = (const float*)d_in[17]; const float* beta = (const float*)d_in[18];
    const float* Wreg = (const float*)d_in[19];  const float* breg = (const float*)d_in[20];
    const float* Wend = (const float*)d_in[21];  const float* bend = (const float*)d_in[22];
    float* out = (float*)d_out;

    int n = in_sizes[0] / FN;
    int E = in_sizes[1] / 2;
    float invE = 1.f / (float)E;
    int nbN = (n + 255) / 256;
    int nbE = (E + 255) / 256;
    int nbW = (n * 32 + 255) / 256;  // warp-per-node grid

    zero_kernel<<<nbN, 256>>>(n);                                     // 0
    hist_kernel<<<nbE, 256>>>(eidx, E);                               // 1
    scan_kernel<<<1, 1024>>>(n);                                      // 2
    scatter_kernel<<<nbE, 256>>>(eidx, ea, E);                        // 3

    // ---- layer 1 (F=2) ----
    transform_kernel<FN, false><<<nbN, 256>>>(x, 0, Wl1, bl1, Wr1, br1, n);     // 4
    gat_aggr_kernel<0><<<nbW, 256>>>(We1, att1, b1, invE, n, 0, nullptr);       // 5
    bn_finalize_kernel<<<1, 32>>>(gamma, beta, 1.f / (float)n);                 // 6

    // ---- layer 2 (F=32, BN+act fused into transform) ----
    transform_kernel<HC, true><<<nbN, 256>>>(x, 0, Wl2, bl2, Wr2, br2, n);      // 7
    gat_aggr_kernel<0><<<nbW, 256>>>(We2, att2, b2, invE, n, 1, nullptr);       // 8
    bn_finalize_kernel<<<1, 32>>>(gamma, beta, 1.f / (float)n);                 // 9

    // ---- layer 3 (F=32, same weights; head fused) ----
    transform_kernel<HC, true><<<nbN, 256>>>(x, 1, Wl2, bl2, Wr2, br2, n);      // 10
    weff_kernel<<<1, 1024>>>(Wreg, breg, Wend, bend);                           // 11
    gat_aggr_kernel<1><<<nbW, 256>>>(We2, att2, b2, invE, n, 0, out);           // 12
}